// round 8
// baseline (speedup 1.0000x reference)
#include <cuda_runtime.h>
#include <cstdint>

#define B_    512
#define T_    2048
#define D_    64
#define H_    66
#define G4    264            // 4*H
#define BPB   4              // batches per block
#define NBLK  (B_ / BPB)     // 128 blocks -> one wave
#define NTHR  320            // warps 0-4 gate role, warps 5-9 proj role
#define PROJ0 160
#define NROW  132            // each worker owns rows j and j+132

__device__ float    g_hT[B_ * H_];
__device__ unsigned g_done = 0;

// ---- packed f32x2 helpers (sm_103a FFMA2 path) ----
#define FMA2(d,a,b,c)   asm("fma.rn.f32x2 %0, %1, %2, %3;" : "=l"(d) : "l"(a), "l"(b), "l"(c))
#define ADD2(d,a,b)     asm("add.rn.f32x2 %0, %1, %2;"     : "=l"(d) : "l"(a), "l"(b))
#define PACK2(d,lo,hi)  asm("mov.b64 %0, {%1, %2};"        : "=l"(d) : "f"(lo), "f"(hi))
#define UNPACK2(lo,hi,s) asm("mov.b64 {%0, %1}, %2;"       : "=f"(lo), "=f"(hi) : "l"(s))

__device__ __forceinline__ float sigm_(float x) {
    return __fdividef(1.f, 1.f + __expf(-x));
}

__global__ __launch_bounds__(NTHR, 1) void fused_lstm_r2(
    const float* __restrict__ x,     const float* __restrict__ W_ih,
    const float* __restrict__ W_hh,  const float* __restrict__ b_ih,
    const float* __restrict__ b_hh,  const float* __restrict__ gamma,
    const float* __restrict__ beta,  const float* __restrict__ fc_w,
    const float* __restrict__ fc_b,  float* __restrict__ out)
{
    __shared__ __align__(16) float sh_h[BPB * 68];       // h rows: 66 + 2 zero pad, 17 chunks
    __shared__ __align__(16) float sh_x[2][BPB][D_];     // double-buffered x rows
    __shared__ __align__(16) float sh_xp[2][BPB][G4];    // double-buffered x-projection
    __shared__ __align__(16) float sh_g[BPB][G4];        // activated gates
    __shared__ float s_a[H_], s_b[H_];
    __shared__ unsigned s_last;

    const int tid = threadIdx.x;
    const int b0  = blockIdx.x * BPB;
    const bool is_gate = (tid < PROJ0);                  // warps 0-4
    const int j   = is_gate ? tid : (tid - PROJ0);       // worker id
    const bool act = (j < NROW);                         // 132 workers per role

    // ---- register-resident weights: 2 rows per worker (j and j+132) ----
    // gate role: W_hh rows, 34 packed pairs each (pair 33 = zeros -> h pad)
    // proj role: W_ih rows, 32 packed pairs each
    unsigned long long wA[34], wB[34];
    float biasA = 0.f, biasB = 0.f;
    if (act) {
        if (is_gate) {
            const float* wa = W_hh + (size_t)j * H_;
            const float* wb = W_hh + (size_t)(j + NROW) * H_;
            #pragma unroll
            for (int i = 0; i < 33; i++) { PACK2(wA[i], wa[2*i], wa[2*i+1]); PACK2(wB[i], wb[2*i], wb[2*i+1]); }
            PACK2(wA[33], 0.f, 0.f); PACK2(wB[33], 0.f, 0.f);
        } else {
            const ulonglong2* wa = (const ulonglong2*)(W_ih + (size_t)j * D_);
            const ulonglong2* wb = (const ulonglong2*)(W_ih + (size_t)(j + NROW) * D_);
            #pragma unroll
            for (int i = 0; i < 16; i++) {
                ulonglong2 va = wa[i]; wA[2*i] = va.x; wA[2*i+1] = va.y;
                ulonglong2 vb = wb[i]; wB[2*i] = vb.x; wB[2*i+1] = vb.y;
            }
            biasA = b_ih[j] + b_hh[j];
            biasB = b_ih[j + NROW] + b_hh[j + NROW];
        }
    }

    // ---- init: zero h (+pads), stage x(0)->buf0, x(1)->buf1 ----
    for (int i = tid; i < BPB * 68; i += NTHR) sh_h[i] = 0.f;
    if (tid < 128) {                                  // 2 buffers x 4 batches x 16 float4
        const int buf = tid >> 6, idx = tid & 63, q = idx >> 4, e = idx & 15;
        ((float4*)sh_x[buf][q])[e] =
            ((const float4*)(x + ((size_t)(b0 + q) * T_ + buf) * D_))[e];
    }
    __syncthreads();

    // proj step: 2 rows x 4 batches; one LDS.128 of x feeds 4 FMA2
    auto proj_step = [&](const float (*xin)[D_], float (*xpout)[G4]) {
        #pragma unroll
        for (int q = 0; q < BPB; q++) {
            const ulonglong2* hp = (const ulonglong2*)xin[q];
            unsigned long long aA0, aA1 = 0ull, aB0, aB1 = 0ull;
            PACK2(aA0, biasA, 0.f); PACK2(aB0, biasB, 0.f);
            #pragma unroll
            for (int k = 0; k < 16; k++) {
                ulonglong2 v = hp[k];
                FMA2(aA0, wA[2*k],   v.x, aA0); FMA2(aA1, wA[2*k+1], v.y, aA1);
                FMA2(aB0, wB[2*k],   v.x, aB0); FMA2(aB1, wB[2*k+1], v.y, aB1);
            }
            ADD2(aA0, aA0, aA1); ADD2(aB0, aB0, aB1);
            float lo, hi;
            UNPACK2(lo, hi, aA0); xpout[q][j]        = lo + hi;
            UNPACK2(lo, hi, aB0); xpout[q][j + NROW] = lo + hi;
        }
    };

    // prologue: xp(0) -> buffer 0
    if (!is_gate && act) proj_step(sh_x[0], sh_xp[0]);
    __syncthreads();

    float c_ = 0.f, h_ = 0.f;
    const int q0 = (tid < G4) ? tid / H_ : 0;    // cell-update mapping (264 cells)
    const int r  = (tid < G4) ? tid % H_ : 0;

    for (int t = 0; t < T_; t++) {
        const int pc = t & 1, pn = pc ^ 1;
        if (is_gate) {
            if (act) {
                // hoist xp(t) reads
                float xpA[BPB], xpB[BPB];
                #pragma unroll
                for (int q = 0; q < BPB; q++) {
                    xpA[q] = sh_xp[pc][q][j];
                    xpB[q] = sh_xp[pc][q][j + NROW];
                }
                // dot(W_hh rows j & j+132, h_q): one LDS.128 -> 4 FMA2
                #pragma unroll
                for (int q = 0; q < BPB; q++) {
                    const ulonglong2* hp = (const ulonglong2*)(sh_h + q * 68);
                    unsigned long long aA0 = 0ull, aA1 = 0ull, aB0 = 0ull, aB1 = 0ull;
                    #pragma unroll
                    for (int k = 0; k < 17; k++) {
                        ulonglong2 v = hp[k];
                        FMA2(aA0, wA[2*k],   v.x, aA0); FMA2(aA1, wA[2*k+1], v.y, aA1);
                        FMA2(aB0, wB[2*k],   v.x, aB0); FMA2(aB1, wB[2*k+1], v.y, aB1);
                    }
                    ADD2(aA0, aA0, aA1); ADD2(aB0, aB0, aB1);
                    float lo, hi;
                    UNPACK2(lo, hi, aA0); const float preA = lo + hi + xpA[q];
                    UNPACK2(lo, hi, aB0); const float preB = lo + hi + xpB[q];
                    // rows [0,132): i/f -> sigmoid.  rows [132,264): g (tanh) if j<66 else o (sigmoid)
                    sh_g[q][j] = sigm_(preA);
                    sh_g[q][j + NROW] = (j < H_) ? (2.f * sigm_(2.f * preB) - 1.f)
                                                 : sigm_(preB);
                }
            }
        } else {
            // ---- proj role: prefetch x(t+2), compute xp(t+1) into buffer pn ----
            float4 pre4;
            const bool do_pre = act && (j < BPB * (D_ / 4)) && (t + 2 < T_);
            const int qq = j >> 4, e = j & 15;
            if (do_pre)
                pre4 = ((const float4*)(x + ((size_t)(b0 + qq) * T_ + (t + 2)) * D_))[e];
            if (act && t + 1 < T_)
                proj_step(sh_x[pn], sh_xp[pn]);
            if (do_pre)
                ((float4*)sh_x[pc][qq])[e] = pre4;   // stage x(t+2) into retired buffer
        }
        __syncthreads();                              // gates + xp(t+1) + x(t+2) published

        if (tid < G4) {                               // cell update: one (q0, r) per thread
            const float i_ = sh_g[q0][r];
            const float f_ = sh_g[q0][H_ + r];
            const float gg = sh_g[q0][2 * H_ + r];
            const float o_ = sh_g[q0][3 * H_ + r];
            c_ = f_ * c_ + i_ * gg;
            const float th = 2.f * sigm_(2.f * c_) - 1.f;
            h_ = o_ * th;
            sh_h[q0 * 68 + r] = h_;
        }
        __syncthreads();                              // h(t) published
    }

    // ---- publish h_T; elect last block ----
    if (tid < G4)
        g_hT[(b0 + q0) * H_ + r] = h_;
    __threadfence();
    __syncthreads();
    if (tid == 0) {
        unsigned old = atomicAdd(&g_done, 1);
        s_last = (old == NBLK - 1) ? 1u : 0u;
    }
    __syncthreads();
    if (!s_last) return;
    if (tid == 0) g_done = 0;            // reset for deterministic graph replay
    __threadfence();

    // ---- BN stats (last block) ----
    if (tid < G4) {
        float s = 0.f, qs = 0.f;
        for (int b = q0 * (B_ / BPB); b < (q0 + 1) * (B_ / BPB); b++) {
            const float v = g_hT[b * H_ + r];
            s += v; qs += v * v;
        }
        sh_g[q0][r] = s;
        sh_h[q0 * 68 + r] = qs;
    }
    __syncthreads();
    if (tid < H_) {
        const float S = sh_g[0][tid] + sh_g[1][tid] + sh_g[2][tid] + sh_g[3][tid];
        const float Q = sh_h[0*68 + tid] + sh_h[1*68 + tid] + sh_h[2*68 + tid] + sh_h[3*68 + tid];
        const float mean = S * (1.f / B_);
        const float var  = Q * (1.f / B_) - mean * mean;
        const float a    = gamma[tid] * rsqrtf(var + 1e-5f);
        s_a[tid] = a * fc_w[tid];
        s_b[tid] = (beta[tid] - mean * a) * fc_w[tid];
    }
    __syncthreads();

    // ---- head ----
    const float f0 = fc_b[0];
    for (int b = tid; b < B_; b += NTHR) {
        float acc = f0;
        #pragma unroll
        for (int jj = 0; jj < H_; jj++)
            acc += s_a[jj] * g_hT[b * H_ + jj] + s_b[jj];
        out[b] = acc;
    }
}

extern "C" void kernel_launch(void* const* d_in, const int* in_sizes, int n_in,
                              void* d_out, int out_size)
{
    const float* x     = (const float*)d_in[0];
    const float* W_ih  = (const float*)d_in[1];
    const float* W_hh  = (const float*)d_in[2];
    const float* b_ih  = (const float*)d_in[3];
    const float* b_hh  = (const float*)d_in[4];
    const float* gamma = (const float*)d_in[5];
    const float* beta  = (const float*)d_in[6];
    const float* fc_w  = (const float*)d_in[7];
    const float* fc_b  = (const float*)d_in[8];
    float* out = (float*)d_out;

    fused_lstm_r2<<<NBLK, NTHR>>>(x, W_ih, W_hh, b_ih, b_hh,
                                  gamma, beta, fc_w, fc_b, out);
}

// round 9
// speedup vs baseline: 1.1060x; 1.1060x over previous
#include <cuda_runtime.h>
#include <cstdint>

#define B_    512
#define T_    2048
#define D_    64
#define H_    66
#define G4    264
#define BG    (B_ * G4)          // x_proj row stride for one t: [T][B][G4]
#define RT    64                 // t-rows per proj tile
#define LBPB  2                  // batches per lstm block
#define LNBLK (B_ / LBPB)        // 256 blocks -> 2 CTAs/SM

__device__ float    g_xproj[(size_t)T_ * B_ * G4];   // [T][B][4H]
__device__ float    g_hT[B_ * H_];
__device__ unsigned g_done = 0;

// ---- packed f32x2 helpers (sm_103a FFMA2 path) ----
#define FMA2(d,a,b,c)   asm("fma.rn.f32x2 %0, %1, %2, %3;" : "=l"(d) : "l"(a), "l"(b), "l"(c))
#define ADD2(d,a,b)     asm("add.rn.f32x2 %0, %1, %2;"     : "=l"(d) : "l"(a), "l"(b))
#define PACK2(d,lo,hi)  asm("mov.b64 %0, {%1, %2};"        : "=l"(d) : "f"(lo), "f"(hi))
#define UNPACK2(lo,hi,s) asm("mov.b64 {%0, %1}, %2;"       : "=f"(lo), "=f"(hi) : "l"(s))

__device__ __forceinline__ float sigm_(float x) {
    return __fdividef(1.f, 1.f + __expf(-x));
}

// ============================================================
// Kernel 1: projection GEMM.  Block = (batch b, 64 consecutive t).
// Thread g holds W_ih row g in regs; x rows broadcast from smem.
// Output layout [T][B][G4]: per (t) the 264 threads write 1056B contiguous.
// ============================================================
__global__ __launch_bounds__(G4, 2) void proj_kernel(
    const float* __restrict__ x, const float* __restrict__ W_ih,
    const float* __restrict__ b_ih, const float* __restrict__ b_hh)
{
    __shared__ __align__(16) float xs[RT * D_];          // 16 KB tile
    const int g  = threadIdx.x;
    const int b  = blockIdx.x >> 5;                      // 512 batches
    const int t0 = (blockIdx.x & 31) * RT;               // 32 tiles of 64 t

    // W_ih row g -> 32 packed f32x2 regs (row is 256B, 16B-aligned)
    unsigned long long w[D_ / 2];
    {
        const ulonglong2* wp = (const ulonglong2*)(W_ih + (size_t)g * D_);
        #pragma unroll
        for (int i = 0; i < D_ / 4; i++) { ulonglong2 v = wp[i]; w[2*i] = v.x; w[2*i+1] = v.y; }
    }
    const float bias = b_ih[g] + b_hh[g];

    // x[b, t0..t0+63, :] is 16KB contiguous
    const float4* xg = (const float4*)(x + ((size_t)b * T_ + t0) * D_);
    for (int i = g; i < RT * D_ / 4; i += G4) ((float4*)xs)[i] = xg[i];
    __syncthreads();

    float* op = g_xproj + (size_t)t0 * BG + b * G4 + g;
    #pragma unroll 2
    for (int r = 0; r < RT; r++) {
        const ulonglong2* hp = (const ulonglong2*)(xs + r * D_);
        unsigned long long a0, a1 = 0ull;
        PACK2(a0, bias, 0.f);
        #pragma unroll
        for (int k = 0; k < D_ / 4; k++) {
            ulonglong2 v = hp[k];
            FMA2(a0, w[2*k],     v.x, a0);
            FMA2(a1, w[2*k + 1], v.y, a1);
        }
        ADD2(a0, a0, a1);
        float lo, hi; UNPACK2(lo, hi, a0);
        op[(size_t)r * BG] = lo + hi;
    }
}

// ============================================================
// Kernel 2: recurrence only.  256 blocks x 264 threads, 2 CTAs/SM.
// Thread g owns W_hh row g; processes 2 batches; xp prefetched from g_xproj.
// ============================================================
__global__ __launch_bounds__(G4, 2) void lstm_kernel(
    const float* __restrict__ W_hh,  const float* __restrict__ gamma,
    const float* __restrict__ beta,  const float* __restrict__ fc_w,
    const float* __restrict__ fc_b,  float* __restrict__ out)
{
    __shared__ __align__(16) float sh_h[LBPB * 68];      // 66 + 2 zero-pad per batch
    __shared__ float sh_g[LBPB * G4];                    // activated gates
    __shared__ float s_S[G4], s_Q[G4];                   // BN tail scratch
    __shared__ float s_a[H_], s_b[H_];
    __shared__ unsigned s_last;

    const int g  = threadIdx.x;
    const int b0 = blockIdx.x * LBPB;

    // W_hh row g -> 34 packed pairs (pair 33 = zeros, covers h pad)
    unsigned long long w[34];
    {
        const float* wr = W_hh + (size_t)g * H_;
        #pragma unroll
        for (int i = 0; i < 33; i++) PACK2(w[i], wr[2*i], wr[2*i + 1]);
        PACK2(w[33], 0.f, 0.f);
    }

    for (int i = g; i < LBPB * 68; i += G4) sh_h[i] = 0.f;

    const float* xpp = g_xproj + (size_t)b0 * G4 + g;    // + t*BG per step
    float xpA = xpp[0];
    float xpB = xpp[G4];

    float c_ = 0.f, h_ = 0.f;
    const int q0 = (g < LBPB * H_) ? g / H_ : 0;         // update mapping (132 cells)
    const int r  = (g < LBPB * H_) ? g % H_ : 0;
    // gate class of row g: [0,132) i/f sigmoid; [132,198) tanh; [198,264) sigmoid
    const bool tg = (g >= 2 * H_) && (g < 3 * H_);
    __syncthreads();

    for (int t = 0; t < T_; t++) {
        // prefetch xp(t+1) — consumed next iteration, a full step of cover
        const size_t toff = (size_t)((t + 1 < T_) ? t + 1 : t) * BG;
        const float xpA_n = xpp[toff];
        const float xpB_n = xpp[toff + G4];

        // dot(W_hh[g,:], h) for both batches; h chunks broadcast (1 wf/instr)
        const ulonglong2* h0 = (const ulonglong2*)(sh_h);
        const ulonglong2* h1 = (const ulonglong2*)(sh_h + 68);
        unsigned long long a0 = 0ull, a1 = 0ull, d0 = 0ull, d1 = 0ull;
        #pragma unroll
        for (int k = 0; k < 17; k++) {
            ulonglong2 v = h0[k];
            ulonglong2 u = h1[k];
            FMA2(a0, w[2*k],     v.x, a0);
            FMA2(a1, w[2*k + 1], v.y, a1);
            FMA2(d0, w[2*k],     u.x, d0);
            FMA2(d1, w[2*k + 1], u.y, d1);
        }
        ADD2(a0, a0, a1); ADD2(d0, d0, d1);
        float lo, hi;
        UNPACK2(lo, hi, a0); const float preA = lo + hi + xpA;
        UNPACK2(lo, hi, d0); const float preB = lo + hi + xpB;

        sh_g[g]      = tg ? (2.f * sigm_(2.f * preA) - 1.f) : sigm_(preA);
        sh_g[G4 + g] = tg ? (2.f * sigm_(2.f * preB) - 1.f) : sigm_(preB);
        __syncthreads();

        if (g < LBPB * H_) {                             // cell update, 132 threads
            const float i_ = sh_g[q0 * G4 + r];
            const float f_ = sh_g[q0 * G4 + H_ + r];
            const float gg = sh_g[q0 * G4 + 2 * H_ + r];
            const float o_ = sh_g[q0 * G4 + 3 * H_ + r];
            c_ = f_ * c_ + i_ * gg;
            const float th = 2.f * sigm_(2.f * c_) - 1.f;
            h_ = o_ * th;
            sh_h[q0 * 68 + r] = h_;
        }
        __syncthreads();
        xpA = xpA_n; xpB = xpB_n;
    }

    // ---- publish h_T; elect last block ----
    if (g < LBPB * H_)
        g_hT[(b0 + q0) * H_ + r] = h_;
    __threadfence();
    __syncthreads();
    if (g == 0) {
        unsigned old = atomicAdd(&g_done, 1);
        s_last = (old == LNBLK - 1) ? 1u : 0u;
    }
    __syncthreads();
    if (!s_last) return;
    if (g == 0) g_done = 0;              // reset for deterministic graph replay
    __threadfence();

    // ---- BN stats (last block): 264 threads = 4 chunks x 66 features ----
    {
        const int qc = g / H_;           // 0..3
        const int rr = g % H_;
        float s = 0.f, qs = 0.f;
        for (int b = qc * (B_ / 4); b < (qc + 1) * (B_ / 4); b++) {
            const float v = g_hT[b * H_ + rr];
            s += v; qs += v * v;
        }
        s_S[g] = s; s_Q[g] = qs;
    }
    __syncthreads();
    if (g < H_) {
        const float S = s_S[g] + s_S[H_ + g] + s_S[2*H_ + g] + s_S[3*H_ + g];
        const float Q = s_Q[g] + s_Q[H_ + g] + s_Q[2*H_ + g] + s_Q[3*H_ + g];
        const float mean = S * (1.f / B_);
        const float var  = Q * (1.f / B_) - mean * mean;
        const float a    = gamma[g] * rsqrtf(var + 1e-5f);
        s_a[g] = a * fc_w[g];
        s_b[g] = (beta[g] - mean * a) * fc_w[g];
    }
    __syncthreads();

    // ---- head ----
    const float f0 = fc_b[0];
    for (int b = g; b < B_; b += G4) {
        float acc = f0;
        #pragma unroll
        for (int jj = 0; jj < H_; jj++)
            acc += s_a[jj] * g_hT[b * H_ + jj] + s_b[jj];
        out[b] = acc;
    }
}

extern "C" void kernel_launch(void* const* d_in, const int* in_sizes, int n_in,
                              void* d_out, int out_size)
{
    const float* x     = (const float*)d_in[0];
    const float* W_ih  = (const float*)d_in[1];
    const float* W_hh  = (const float*)d_in[2];
    const float* b_ih  = (const float*)d_in[3];
    const float* b_hh  = (const float*)d_in[4];
    const float* gamma = (const float*)d_in[5];
    const float* beta  = (const float*)d_in[6];
    const float* fc_w  = (const float*)d_in[7];
    const float* fc_b  = (const float*)d_in[8];
    float* out = (float*)d_out;

    proj_kernel<<<B_ * (T_ / RT), G4>>>(x, W_ih, b_ih, b_hh);
    lstm_kernel<<<LNBLK, G4>>>(W_hh, gamma, beta, fc_w, fc_b, out);
}

// round 11
// speedup vs baseline: 1.4866x; 1.3442x over previous
#include <cuda_runtime.h>
#include <cuda_bf16.h>
#include <cstdint>

#define B_    512
#define T_    2048
#define D_    64
#define H_    66
#define G4    264
#define BG    (B_ * G4)          // x_proj stride per t: [T][B][G4]
#define MT    128                // t-rows per proj block
#define PADW  72                 // padded row length (bf16) -> 144B, conflict-free LDSM
#define LBPB  2
#define LNBLK (B_ / LBPB)

__device__ float    g_xproj[(size_t)T_ * B_ * G4];   // raw GEMM (no bias)
__device__ float    g_hT[B_ * H_];
__device__ unsigned g_done = 0;

// ================= packed f32x2 helpers (lstm path) =================
#define FMA2(d,a,b,c)   asm("fma.rn.f32x2 %0, %1, %2, %3;" : "=l"(d) : "l"(a), "l"(b), "l"(c))
#define ADD2(d,a,b)     asm("add.rn.f32x2 %0, %1, %2;"     : "=l"(d) : "l"(a), "l"(b))
#define PACK2(d,lo,hi)  asm("mov.b64 %0, {%1, %2};"        : "=l"(d) : "f"(lo), "f"(hi))
#define UNPACK2(lo,hi,s) asm("mov.b64 {%0, %1}, %2;"       : "=f"(lo), "=f"(hi) : "l"(s))

__device__ __forceinline__ float sigm_(float x) {
    return __fdividef(1.f, 1.f + __expf(-x));
}

// ================= mma.sync helpers (sm_80+ baseline, compiles for compute_103) =================
__device__ __forceinline__ uint32_t smem_u32(const void* p) {
    uint32_t a;
    asm("{ .reg .u64 t; cvta.to.shared.u64 t, %1; cvt.u32.u64 %0, t; }" : "=r"(a) : "l"(p));
    return a;
}
#define LDSM_X4(r, a) \
    asm volatile("ldmatrix.sync.aligned.m8n8.x4.shared.b16 {%0,%1,%2,%3}, [%4];" \
        : "=r"((r)[0]),"=r"((r)[1]),"=r"((r)[2]),"=r"((r)[3]) : "r"(a))
#define LDSM_X2(r, a) \
    asm volatile("ldmatrix.sync.aligned.m8n8.x2.shared.b16 {%0,%1}, [%2];" \
        : "=r"((r)[0]),"=r"((r)[1]) : "r"(a))
#define MMA_BF16(d, a, bb) \
    asm volatile("mma.sync.aligned.m16n8k16.row.col.f32.bf16.bf16.f32 " \
        "{%0,%1,%2,%3}, {%4,%5,%6,%7}, {%8,%9}, {%0,%1,%2,%3};" \
        : "+f"((d)[0]),"+f"((d)[1]),"+f"((d)[2]),"+f"((d)[3]) \
        : "r"((a)[0]),"r"((a)[1]),"r"((a)[2]),"r"((a)[3]), "r"((bb)[0]),"r"((bb)[1]))

__device__ __forceinline__ uint32_t pack_bf16(__nv_bfloat16 lo, __nv_bfloat16 hi) {
    return ((uint32_t)__bfloat16_as_ushort(hi) << 16) | (uint32_t)__bfloat16_as_ushort(lo);
}
// split float4 into bf16 hi pair-regs and lo (residual) pair-regs
__device__ __forceinline__ void split_f4(float4 v, uint2& h, uint2& l) {
    const __nv_bfloat16 h0 = __float2bfloat16(v.x), h1 = __float2bfloat16(v.y),
                        h2 = __float2bfloat16(v.z), h3 = __float2bfloat16(v.w);
    h.x = pack_bf16(h0, h1); h.y = pack_bf16(h2, h3);
    l.x = pack_bf16(__float2bfloat16(v.x - __bfloat162float(h0)),
                    __float2bfloat16(v.y - __bfloat162float(h1)));
    l.y = pack_bf16(__float2bfloat16(v.z - __bfloat162float(h2)),
                    __float2bfloat16(v.w - __bfloat162float(h3)));
}

// smem byte offsets for proj_mma
#define XS_HI 0
#define XS_LO (XS_HI + MT * PADW * 2)        // 18432
#define WS_HI (XS_LO + MT * PADW * 2)        // 36864
#define WS_LO (WS_HI + G4 * PADW * 2)        // 74880
#define PSM_TOT (WS_LO + G4 * PADW * 2)      // 112896

// ================= projection: HMMA bf16-split GEMM =================
// out[t0+m][b][n] = sum_k x[b,t0+m,k] * W_ih[n,k]   (bias added by lstm kernel)
__global__ __launch_bounds__(256, 1) void proj_mma(const float* __restrict__ x,
                                                   const float* __restrict__ W_ih)
{
    extern __shared__ __align__(16) char smem[];
    const uint32_t sb = smem_u32(smem);
    const int tid  = threadIdx.x;
    const int w    = tid >> 5, lane = tid & 31;
    const int b    = blockIdx.x >> 4;
    const int t0   = (blockIdx.x & 15) * MT;

    // ---- load + split W_ih (264 x 64 f32) into WS_HI/WS_LO ----
    {
        const float4* wg = (const float4*)W_ih;
        for (int i = tid; i < G4 * (D_ / 4); i += 256) {
            const int row = i >> 4, c4 = (i & 15) * 4;
            uint2 h, l; split_f4(wg[i], h, l);
            const uint32_t off = (uint32_t)(row * PADW + c4) * 2;
            *(uint2*)(smem + WS_HI + off) = h;
            *(uint2*)(smem + WS_LO + off) = l;
        }
    }
    // ---- load + split x tile (128 x 64 f32) into XS_HI/XS_LO ----
    {
        const float4* xg = (const float4*)(x + ((size_t)b * T_ + t0) * D_);
        for (int i = tid; i < MT * (D_ / 4); i += 256) {
            const int row = i >> 4, c4 = (i & 15) * 4;
            uint2 h, l; split_f4(xg[i], h, l);
            const uint32_t off = (uint32_t)(row * PADW + c4) * 2;
            *(uint2*)(smem + XS_HI + off) = h;
            *(uint2*)(smem + XS_LO + off) = l;
        }
    }
    __syncthreads();

    // ---- A fragments (this warp's 16 m-rows, all 4 k-chunks, hi+lo) ----
    uint32_t aHi[4][4], aLo[4][4];
    {
        const int mat = lane >> 3, r = lane & 7;
        const int row = 16 * w + ((mat & 1) << 3) + r;     // m0:rows0-7,k0 m1:rows8-15,k0 m2:k+8 m3:rows8-15,k+8
        const int colb = (mat >> 1) << 3;
        #pragma unroll
        for (int kc = 0; kc < 4; kc++) {
            const uint32_t o = (uint32_t)(row * PADW + kc * 16 + colb) * 2;
            LDSM_X4(aHi[kc], sb + XS_HI + o);
            LDSM_X4(aLo[kc], sb + XS_LO + o);
        }
    }

    // ---- n-tile loop: 33 tiles of 8 gate columns ----
    const int L = lane & 15;                                // x2 uses lanes 0-15; replicate above
    const int nr   = L & 7;                                 // row within 8-row B tile
    const int colb = (L >> 3) << 3;                         // k offset 0 / 8
    const int mrow = lane >> 2;                             // C fragment row (0..7)
    const int ccol = (lane & 3) * 2;                        // C fragment col pair

    for (int nt = 0; nt < 33; nt++) {
        uint32_t bHi[4][2], bLo[4][2];
        const int n = nt * 8 + nr;
        #pragma unroll
        for (int kc = 0; kc < 4; kc++) {
            const uint32_t o = (uint32_t)(n * PADW + kc * 16 + colb) * 2;
            LDSM_X2(bHi[kc], sb + WS_HI + o);
            LDSM_X2(bLo[kc], sb + WS_LO + o);
        }
        float c[4] = {0.f, 0.f, 0.f, 0.f};
        #pragma unroll
        for (int kc = 0; kc < 4; kc++) {
            MMA_BF16(c, aHi[kc], bHi[kc]);
            MMA_BF16(c, aHi[kc], bLo[kc]);
            MMA_BF16(c, aLo[kc], bHi[kc]);
        }
        // C mapping: c0,c1 -> (row=mrow, col=ccol,ccol+1); c2,c3 -> row+8
        float* op = g_xproj + (size_t)(t0 + 16 * w + mrow) * BG
                  + (size_t)b * G4 + nt * 8 + ccol;
        *(float2*)op                      = make_float2(c[0], c[1]);
        *(float2*)(op + (size_t)8 * BG)   = make_float2(c[2], c[3]);
    }
}

// ================= recurrence (R9 passing code + bias folded) =================
__global__ __launch_bounds__(G4, 2) void lstm_kernel(
    const float* __restrict__ W_hh,  const float* __restrict__ b_ih,
    const float* __restrict__ b_hh,  const float* __restrict__ gamma,
    const float* __restrict__ beta,  const float* __restrict__ fc_w,
    const float* __restrict__ fc_b,  float* __restrict__ out)
{
    __shared__ __align__(16) float sh_h[LBPB * 68];
    __shared__ float sh_g[LBPB * G4];
    __shared__ float s_S[G4], s_Q[G4];
    __shared__ float s_a[H_], s_b[H_];
    __shared__ unsigned s_last;

    const int g  = threadIdx.x;
    const int b0 = blockIdx.x * LBPB;

    unsigned long long w[34];
    {
        const float* wr = W_hh + (size_t)g * H_;
        #pragma unroll
        for (int i = 0; i < 33; i++) PACK2(w[i], wr[2*i], wr[2*i + 1]);
        PACK2(w[33], 0.f, 0.f);
    }
    const float biasg = b_ih[g] + b_hh[g];

    for (int i = g; i < LBPB * 68; i += G4) sh_h[i] = 0.f;

    const float* xpp = g_xproj + (size_t)b0 * G4 + g;
    float xpA = xpp[0]  + biasg;
    float xpB = xpp[G4] + biasg;

    float c_ = 0.f, h_ = 0.f;
    const int q0 = (g < LBPB * H_) ? g / H_ : 0;
    const int r  = (g < LBPB * H_) ? g % H_ : 0;
    const bool tg = (g >= 2 * H_) && (g < 3 * H_);
    __syncthreads();

    for (int t = 0; t < T_; t++) {
        const size_t toff = (size_t)((t + 1 < T_) ? t + 1 : t) * BG;
        const float xpA_n = xpp[toff]      + biasg;
        const float xpB_n = xpp[toff + G4] + biasg;

        const ulonglong2* h0 = (const ulonglong2*)(sh_h);
        const ulonglong2* h1 = (const ulonglong2*)(sh_h + 68);
        unsigned long long a0 = 0ull, a1 = 0ull, d0 = 0ull, d1 = 0ull;
        #pragma unroll
        for (int k = 0; k < 17; k++) {
            ulonglong2 v = h0[k];
            ulonglong2 u = h1[k];
            FMA2(a0, w[2*k],     v.x, a0);
            FMA2(a1, w[2*k + 1], v.y, a1);
            FMA2(d0, w[2*k],     u.x, d0);
            FMA2(d1, w[2*k + 1], u.y, d1);
        }
        ADD2(a0, a0, a1); ADD2(d0, d0, d1);
        float lo, hi;
        UNPACK2(lo, hi, a0); const float preA = lo + hi + xpA;
        UNPACK2(lo, hi, d0); const float preB = lo + hi + xpB;

        sh_g[g]      = tg ? (2.f * sigm_(2.f * preA) - 1.f) : sigm_(preA);
        sh_g[G4 + g] = tg ? (2.f * sigm_(2.f * preB) - 1.f) : sigm_(preB);
        __syncthreads();

        if (g < LBPB * H_) {
            const float i_ = sh_g[q0 * G4 + r];
            const float f_ = sh_g[q0 * G4 + H_ + r];
            const float gg = sh_g[q0 * G4 + 2 * H_ + r];
            const float o_ = sh_g[q0 * G4 + 3 * H_ + r];
            c_ = f_ * c_ + i_ * gg;
            const float th = 2.f * sigm_(2.f * c_) - 1.f;
            h_ = o_ * th;
            sh_h[q0 * 68 + r] = h_;
        }
        __syncthreads();
        xpA = xpA_n; xpB = xpB_n;
    }

    if (g < LBPB * H_)
        g_hT[(b0 + q0) * H_ + r] = h_;
    __threadfence();
    __syncthreads();
    if (g == 0) {
        unsigned old = atomicAdd(&g_done, 1);
        s_last = (old == LNBLK - 1) ? 1u : 0u;
    }
    __syncthreads();
    if (!s_last) return;
    if (g == 0) g_done = 0;
    __threadfence();

    {
        const int qc = g / H_;
        const int rr = g % H_;
        float s = 0.f, qs = 0.f;
        for (int b = qc * (B_ / 4); b < (qc + 1) * (B_ / 4); b++) {
            const float v = g_hT[b * H_ + rr];
            s += v; qs += v * v;
        }
        s_S[g] = s; s_Q[g] = qs;
    }
    __syncthreads();
    if (g < H_) {
        const float S = s_S[g] + s_S[H_ + g] + s_S[2*H_ + g] + s_S[3*H_ + g];
        const float Q = s_Q[g] + s_Q[H_ + g] + s_Q[2*H_ + g] + s_Q[3*H_ + g];
        const float mean = S * (1.f / B_);
        const float var  = Q * (1.f / B_) - mean * mean;
        const float a    = gamma[g] * rsqrtf(var + 1e-5f);
        s_a[g] = a * fc_w[g];
        s_b[g] = (beta[g] - mean * a) * fc_w[g];
    }
    __syncthreads();

    const float f0 = fc_b[0];
    for (int b = g; b < B_; b += G4) {
        float acc = f0;
        #pragma unroll
        for (int jj = 0; jj < H_; jj++)
            acc += s_a[jj] * g_hT[b * H_ + jj] + s_b[jj];
        out[b] = acc;
    }
}

// ================= launch =================
extern "C" void kernel_launch(void* const* d_in, const int* in_sizes, int n_in,
                              void* d_out, int out_size)
{
    const float* x     = (const float*)d_in[0];
    const float* W_ih  = (const float*)d_in[1];
    const float* W_hh  = (const float*)d_in[2];
    const float* b_ih  = (const float*)d_in[3];
    const float* b_hh  = (const float*)d_in[4];
    const float* gamma = (const float*)d_in[5];
    const float* beta  = (const float*)d_in[6];
    const float* fc_w  = (const float*)d_in[7];
    const float* fc_b  = (const float*)d_in[8];
    float* out = (float*)d_out;

    static bool attr_set = false;
    if (!attr_set) {
        cudaFuncSetAttribute(proj_mma, cudaFuncAttributeMaxDynamicSharedMemorySize, PSM_TOT);
        attr_set = true;
    }

    proj_mma<<<B_ * (T_ / MT), 256, PSM_TOT>>>(x, W_ih);
    lstm_kernel<<<LNBLK, G4>>>(W_hh, b_ih, b_hh, gamma, beta, fc_w, fc_b, out);
}